// round 6
// baseline (speedup 1.0000x reference)
#include <cuda_runtime.h>
#include <math.h>

#define Bsz 4
#define Ssz 8192
#define Dsz 1024
#define Nsz 12
#define NBLK 128
#define NTHR 512
#define CH 256              // rows per block
#define SUB 64              // rows per subchunk (4 subchunks)

typedef unsigned long long u64;

// Scratch (allocation-free rule: __device__ globals)
__device__ u64   g_wdup[(size_t)Bsz * Ssz * Nsz];        // 3 MB, w duplicated lo=hi
__device__ float g_Upart[(size_t)NBLK * 2 * Nsz * Dsz];  // 12.6 MB
__device__ float g_U[48 * Dsz];
__device__ float g_SV[48 * Dsz];
__device__ float g_T[48 * Dsz];
__device__ unsigned g_barcnt[4];                         // zero-init; monotonic

// ---- packed f32x2 helpers -------------------------------------------------
__device__ __forceinline__ void ffma2(u64& d, u64 a, u64 b) {
    asm("fma.rn.f32x2 %0, %1, %2, %0;" : "+l"(d) : "l"(a), "l"(b));
}
__device__ __forceinline__ float2 u2f(u64 v) {
    float2 f;
    asm("mov.b64 {%0,%1}, %2;" : "=f"(f.x), "=f"(f.y) : "l"(v));
    return f;
}
__device__ __forceinline__ u64 f2u(float lo, float hi) {
    u64 v;
    asm("mov.b64 %0, {%1,%2};" : "=l"(v) : "f"(lo), "f"(hi));
    return v;
}

// ---- replay-safe grid barrier (monotonic generation counter) --------------
__device__ __forceinline__ void gridbar(int k) {
    __syncthreads();
    __threadfence();
    if (threadIdx.x == 0) {
        unsigned pos = atomicAdd(&g_barcnt[k], 1u);
        unsigned target = (pos / NBLK + 1u) * NBLK;
        unsigned v;
        do {
            __nanosleep(32);
            asm volatile("ld.acquire.gpu.u32 %0, [%1];" : "=r"(v) : "l"(&g_barcnt[k]));
        } while (v < target);
    }
    __syncthreads();
}

union SmemU {
    struct { u64 wdup[CH][Nsz]; float part[SUB][4][14]; } k1;   // 24K + 14.3K
    struct { float As[64][49]; float Ws[64][66]; } g;           // 29.4K
    struct { u64 wd[CH][Nsz]; } e;                              // 24K
};

__global__ void __launch_bounds__(NTHR, 1)
fused_all(const float* __restrict__ x, const float* __restrict__ centers,
          const float* __restrict__ scales, const float* __restrict__ amps,
          const float* __restrict__ w_value, const float* __restrict__ w_output,
          float* __restrict__ out) {
    __shared__ SmemU sm;
    __shared__ float c2s[Nsz], invs[Nsz], ampv[Nsz];

    const int t = threadIdx.x, lane = t & 31, w = t >> 5;
    const int b = blockIdx.x >> 5, chunk = blockIdx.x & 31;
    const size_t row0 = (size_t)b * Ssz + (size_t)chunk * CH;

    // ---- params: c2[n] (warps 0..11), sigma/amp (t<12) ----
    if (w < Nsz) {
        const float* cn = centers + w * Dsz + lane * 4;
        float s = 0.f;
        #pragma unroll
        for (int j = 0; j < 8; j++) {
            float4 v = __ldg((const float4*)(cn + j * 128));
            s += v.x * v.x + v.y * v.y + v.z * v.z + v.w * v.w;
        }
        #pragma unroll
        for (int o = 16; o > 0; o >>= 1) s += __shfl_down_sync(0xffffffffu, s, o);
        if (lane == 0) c2s[w] = s;
    }
    if (t < Nsz) {
        float sv = expf(scales[t]);
        sv = fminf(fmaxf(sv, 0.1f), 2.0f);
        invs[t] = 0.5f / (sv * sv);
        ampv[t] = 1.f / (1.f + expf(-amps[t]));
    }
    __syncthreads();

    // ================= PHASE A: splat weights (warp per row-pair) ==========
    for (int sub = 0; sub < 4; sub++) {
        #pragma unroll 1
        for (int pr = 0; pr < 2; pr++) {
            const int rloc = w * 4 + pr * 2;               // local row in subchunk
            const float* xA = x + (row0 + sub * SUB + rloc) * Dsz + lane * 4;
            const float* xB = xA + Dsz;
            u64 pa[13], pb[13];
            #pragma unroll
            for (int i = 0; i < 13; i++) { pa[i] = 0ull; pb[i] = 0ull; }
            #pragma unroll
            for (int h = 0; h < 2; h++) {
                ulonglong2 xa[4], xb[4];
                #pragma unroll
                for (int c = 0; c < 4; c++) {
                    xa[c] = *(const ulonglong2*)(xA + (h * 4 + c) * 128);
                    xb[c] = *(const ulonglong2*)(xB + (h * 4 + c) * 128);
                }
                #pragma unroll
                for (int c = 0; c < 4; c++) {
                    const float* cp = centers + (h * 4 + c) * 128 + lane * 4;
                    #pragma unroll
                    for (int n = 0; n < Nsz; n++) {
                        ulonglong2 cv = *(const ulonglong2*)(cp + n * Dsz);
                        ffma2(pa[n], xa[c].x, cv.x);
                        ffma2(pa[n], xa[c].y, cv.y);
                        ffma2(pb[n], xb[c].x, cv.x);
                        ffma2(pb[n], xb[c].y, cv.y);
                    }
                    ffma2(pa[12], xa[c].x, xa[c].x);
                    ffma2(pa[12], xa[c].y, xa[c].y);
                    ffma2(pb[12], xb[c].x, xb[c].x);
                    ffma2(pb[12], xb[c].y, xb[c].y);
                }
            }
            // collapse + 3-stage xor fold -> lanes 0..3 hold 4 partial sums
            #pragma unroll
            for (int i = 0; i < 13; i++) {
                float2 fa = u2f(pa[i]); float va = fa.x + fa.y;
                float2 fb = u2f(pb[i]); float vb = fb.x + fb.y;
                va += __shfl_xor_sync(0xffffffffu, va, 16);
                vb += __shfl_xor_sync(0xffffffffu, vb, 16);
                va += __shfl_xor_sync(0xffffffffu, va, 8);
                vb += __shfl_xor_sync(0xffffffffu, vb, 8);
                va += __shfl_xor_sync(0xffffffffu, va, 4);
                vb += __shfl_xor_sync(0xffffffffu, vb, 4);
                if (lane < 4) {
                    sm.k1.part[rloc    ][lane][i] = va;
                    sm.k1.part[rloc + 1][lane][i] = vb;
                }
            }
        }
        __syncthreads();
        // finalize 64 rows in parallel
        if (t < SUB) {
            float red[13];
            #pragma unroll
            for (int i = 0; i < 13; i++)
                red[i] = (sm.k1.part[t][0][i] + sm.k1.part[t][1][i]) +
                         (sm.k1.part[t][2][i] + sm.k1.part[t][3][i]);
            float g[Nsz], ssum = 0.f;
            #pragma unroll
            for (int n = 0; n < Nsz; n++) {
                float d2 = fmaxf(red[12] + c2s[n] - 2.f * red[n], 0.f);
                g[n] = __expf(-d2 * invs[n]) * ampv[n];
                ssum += g[n];
            }
            float inv = 1.f / fmaxf(ssum, 1e-8f);
            #pragma unroll
            for (int n = 0; n < Nsz; n++) {
                float wv = g[n] * inv;
                sm.k1.wdup[sub * SUB + t][n] = f2u(wv, wv);
            }
        }
        __syncthreads();
    }
    // write w to gmem (coalesced u64 copy)
    for (int i = t; i < CH * Nsz; i += NTHR)
        g_wdup[row0 * Nsz + i] = ((const u64*)sm.k1.wdup)[i];

    // ================= PHASE B: U partials (thread per d4, half-split) =====
    {
        const int half = t >> 8, d4 = t & 255;
        ulonglong2 acc[Nsz];
        #pragma unroll
        for (int n = 0; n < Nsz; n++) { acc[n].x = 0ull; acc[n].y = 0ull; }

        for (int sub = 3; sub >= 0; sub--) {          // reverse: L2-hot first
            const int base = sub * SUB + half * 32;
            #pragma unroll 1
            for (int rb = 0; rb < 32; rb += 8) {
                ulonglong2 xv[8];
                #pragma unroll
                for (int j = 0; j < 8; j++)
                    xv[j] = *(const ulonglong2*)(x + (row0 + base + rb + j) * Dsz + d4 * 4);
                #pragma unroll
                for (int j = 0; j < 8; j++) {
                    const ulonglong2* wp = (const ulonglong2*)sm.k1.wdup[base + rb + j];
                    #pragma unroll
                    for (int p = 0; p < 6; p++) {
                        ulonglong2 q = wp[p];
                        ffma2(acc[2 * p    ].x, q.x, xv[j].x);
                        ffma2(acc[2 * p    ].y, q.x, xv[j].y);
                        ffma2(acc[2 * p + 1].x, q.y, xv[j].x);
                        ffma2(acc[2 * p + 1].y, q.y, xv[j].y);
                    }
                }
            }
        }
        float* up = g_Upart + ((size_t)blockIdx.x * 2 + half) * Nsz * Dsz + d4 * 4;
        #pragma unroll
        for (int n = 0; n < Nsz; n++) *(ulonglong2*)(up + n * Dsz) = acc[n];
    }
    gridbar(0);

    // ================= REDUCE: Upart -> U; zero SV, T ======================
    {
        unsigned item = blockIdx.x * NTHR + t;
        if (item < 48u * 256u) {
            int bn = item >> 8, dd = item & 255;
            int bb = bn / Nsz, nn = bn % Nsz;
            float4 s = make_float4(0.f, 0.f, 0.f, 0.f);
            #pragma unroll 4
            for (int c = 0; c < 64; c++) {            // sets bb*64 .. bb*64+63
                const float4 v = *(const float4*)(g_Upart +
                    ((size_t)(bb * 64 + c) * Nsz + nn) * Dsz + dd * 4);
                s.x += v.x; s.y += v.y; s.z += v.z; s.w += v.w;
            }
            *(float4*)(g_U + bn * Dsz + dd * 4) = s;
            float4 z = make_float4(0.f, 0.f, 0.f, 0.f);
            *(float4*)(g_SV + bn * Dsz + dd * 4) = z;
            *(float4*)(g_T + bn * Dsz + dd * 4) = z;
        }
    }
    gridbar(1);

    // ================= GEMMS: 48 x 1024 x 1024, K-split ====================
    for (int phase = 0; phase < 2; phase++) {
        const float* A = phase ? g_SV : g_U;
        const float* W = phase ? w_output : w_value;
        float* C = phase ? g_T : g_SV;
        for (int tile = blockIdx.x; tile < 256; tile += NBLK) {
            int e0 = (tile & 15) * 64, k0 = (tile >> 4) * 64;
            __syncthreads();
            for (int idx = t; idx < 48 * 64; idx += NTHR) {
                int m = idx >> 6, kk = idx & 63;
                sm.g.As[kk][m] = __ldg(A + (size_t)m * Dsz + k0 + kk);
            }
            for (int idx = t; idx < 64 * 64; idx += NTHR) {
                int e = idx >> 6, kk = idx & 63;
                sm.g.Ws[kk][e] = __ldg(W + (size_t)(e0 + e) * Dsz + k0 + kk);
            }
            __syncthreads();
            int ty = t >> 6, tx = t & 63;
            float a0[6] = {0.f, 0.f, 0.f, 0.f, 0.f, 0.f};
            #pragma unroll 4
            for (int kk = 0; kk < 64; kk++) {
                float wv = sm.g.Ws[kk][tx];
                #pragma unroll
                for (int i = 0; i < 6; i++) a0[i] += sm.g.As[kk][ty * 6 + i] * wv;
            }
            #pragma unroll
            for (int i = 0; i < 6; i++)
                atomicAdd(&C[(size_t)(ty * 6 + i) * Dsz + e0 + tx], a0[i]);
        }
        gridbar(2 + phase);
    }

    // ================= EXPAND: out = sum_n w * T ===========================
    {
        for (int i = t; i < CH * Nsz; i += NTHR)
            ((u64*)sm.e.wd)[i] = g_wdup[row0 * Nsz + i];
        u64 trp[Nsz];
        #pragma unroll
        for (int n = 0; n < Nsz; n++)
            trp[n] = *(const u64*)(g_T + (size_t)(b * Nsz + n) * Dsz + t * 2);
        __syncthreads();
        #pragma unroll 2
        for (int r = 0; r < CH; r++) {
            const ulonglong2* wp = (const ulonglong2*)sm.e.wd[r];
            u64 o = 0ull;
            #pragma unroll
            for (int p = 0; p < 6; p++) {
                ulonglong2 q = wp[p];
                ffma2(o, q.x, trp[2 * p]);
                ffma2(o, q.y, trp[2 * p + 1]);
            }
            *(u64*)(out + (row0 + r) * Dsz + t * 2) = o;
        }
    }
}

extern "C" void kernel_launch(void* const* d_in, const int* in_sizes, int n_in,
                              void* d_out, int out_size) {
    const float* x        = (const float*)d_in[0];
    const float* centers  = (const float*)d_in[1];
    const float* scales   = (const float*)d_in[2];
    const float* amps     = (const float*)d_in[3];
    const float* w_value  = (const float*)d_in[4];
    const float* w_output = (const float*)d_in[5];
    float* out = (float*)d_out;

    fused_all<<<NBLK, NTHR>>>(x, centers, scales, amps, w_value, w_output, out);
}

// round 7
// speedup vs baseline: 5.1231x; 5.1231x over previous
#include <cuda_runtime.h>
#include <math.h>

#define Bsz 4
#define Ssz 8192
#define Dsz 1024
#define Nsz 12
#define NROWS (Bsz*Ssz)
#define K1BLK 512
#define RPB 64              // rows per K1 block
#define K2BLK 128

typedef unsigned long long u64;

// Scratch (allocation-free rule: __device__ globals)
__device__ u64   g_wdup[(size_t)NROWS * Nsz];            // 3 MB, w duplicated lo=hi
__device__ float g_Upart[(size_t)K1BLK * Nsz * Dsz];     // 25.2 MB (written only when flagged)
__device__ unsigned char g_rowflag[NROWS];               // 1 = row has nonzero w
__device__ int   g_flags[K1BLK];                         // per-chunk nonzero flag
__device__ float g_U[48 * Dsz];
__device__ float g_SV[48 * Dsz];
__device__ float g_T[48 * Dsz];
__device__ unsigned g_barcnt[4];                         // zero-init; monotonic

// ---- packed f32x2 helpers -------------------------------------------------
__device__ __forceinline__ void ffma2(u64& d, u64 a, u64 b) {
    asm("fma.rn.f32x2 %0, %1, %2, %0;" : "+l"(d) : "l"(a), "l"(b));
}
__device__ __forceinline__ u64 f2u(float lo, float hi) {
    u64 v;
    asm("mov.b64 %0, {%1,%2};" : "=l"(v) : "f"(lo), "f"(hi));
    return v;
}

// ---- replay-safe grid barrier (monotonic generation counter) --------------
__device__ __forceinline__ void gridbar(int k) {
    __syncthreads();
    __threadfence();
    if (threadIdx.x == 0) {
        unsigned pos = atomicAdd(&g_barcnt[k], 1u);
        unsigned target = (pos / K2BLK + 1u) * K2BLK;
        unsigned v;
        do {
            __nanosleep(20);
            asm volatile("ld.acquire.gpu.u32 %0, [%1];" : "=r"(v) : "l"(&g_barcnt[k]));
        } while (v < target);
    }
    __syncthreads();
}

// ===========================================================================
// K1: splat weights with exact underflow short-circuit + gated U partials.
// 512 blocks x 256 thr; warp-per-row (8 rows/warp).
// ===========================================================================
__global__ void __launch_bounds__(256)
k1(const float* __restrict__ x, const float* __restrict__ centers,
   const float* __restrict__ scales, const float* __restrict__ amps) {
    __shared__ float c2s[Nsz], sqc2[Nsz], invs[Nsz], ampv[Nsz];
    __shared__ u64 wsm[RPB][Nsz];
    __shared__ int anynz;

    const int t = threadIdx.x, lane = t & 31, wid = t >> 5;
    const int bid = blockIdx.x;
    const size_t row0 = (size_t)bid * RPB;

    // params: warps 0..7 cover centers n = wid, wid+8
    for (int n = wid; n < Nsz; n += 8) {
        const float* cn = centers + (size_t)n * Dsz + lane * 4;
        float s = 0.f;
        #pragma unroll
        for (int j = 0; j < 8; j++) {
            float4 v = __ldg((const float4*)(cn + j * 128));
            s += v.x * v.x + v.y * v.y + v.z * v.z + v.w * v.w;
        }
        #pragma unroll
        for (int o = 16; o > 0; o >>= 1) s += __shfl_xor_sync(0xffffffffu, s, o);
        if (lane == 0) { c2s[n] = s; sqc2[n] = sqrtf(s); }
    }
    if (t < Nsz) {
        float sv = expf(scales[t]);
        sv = fminf(fmaxf(sv, 0.1f), 2.0f);
        invs[t] = 0.5f / (sv * sv);
        ampv[t] = 1.f / (1.f + expf(-amps[t]));
    }
    if (t == 0) anynz = 0;
    __syncthreads();

    #pragma unroll 1
    for (int r = 0; r < 8; r++) {
        const int rloc = wid * 8 + r;
        const float* xr = x + (row0 + rloc) * Dsz + lane * 4;
        float4 v[8];
        #pragma unroll
        for (int j = 0; j < 8; j++) v[j] = __ldg((const float4*)(xr + j * 128));
        float p = 0.f;
        #pragma unroll
        for (int j = 0; j < 8; j++)
            p += v[j].x * v[j].x + v[j].y * v[j].y + v[j].z * v[j].z + v[j].w * v[j].w;
        #pragma unroll
        for (int o = 16; o > 0; o >>= 1) p += __shfl_xor_sync(0xffffffffu, p, o);
        const float x2 = p;

        // exact skip bound: d2 >= (|x|-|c|)^2 ; exp(-v)==0 in fp32 for v>103.9
        bool ok = true;
        if (lane < Nsz) {
            float dm = sqrtf(x2) - sqc2[lane];
            ok = (dm * dm) * invs[lane] > 120.0f;
        }
        if (__ballot_sync(0xffffffffu, ok) == 0xffffffffu) {
            if (lane < Nsz) wsm[rloc][lane] = 0ull;
            if (lane == 0) g_rowflag[row0 + rloc] = 0;
        } else {
            // slow path: full dots (correct for arbitrary inputs)
            float pn[Nsz];
            #pragma unroll
            for (int n = 0; n < Nsz; n++) pn[n] = 0.f;
            #pragma unroll 1
            for (int j = 0; j < 8; j++) {
                float4 xv = v[j];
                #pragma unroll
                for (int n = 0; n < Nsz; n++) {
                    float4 c4 = __ldg((const float4*)(centers + (size_t)n * Dsz + j * 128 + lane * 4));
                    pn[n] += xv.x * c4.x + xv.y * c4.y + xv.z * c4.z + xv.w * c4.w;
                }
            }
            #pragma unroll
            for (int n = 0; n < Nsz; n++) {
                #pragma unroll
                for (int o = 16; o > 0; o >>= 1)
                    pn[n] += __shfl_xor_sync(0xffffffffu, pn[n], o);
            }
            float sum = 0.f, gl = 0.f;
            #pragma unroll
            for (int n = 0; n < Nsz; n++) {
                float d2 = fmaxf(x2 + c2s[n] - 2.f * pn[n], 0.f);
                float gg = expf(-d2 * invs[n]) * ampv[n];
                sum += gg;
                if (lane == n) gl = gg;
            }
            float inv = 1.f / fmaxf(sum, 1e-8f);
            if (lane < Nsz) wsm[rloc][lane] = f2u(gl * inv, gl * inv);
            if (lane == 0) {
                g_rowflag[row0 + rloc] = (sum > 0.f) ? 1 : 0;
                if (sum > 0.f) anynz = 1;
            }
        }
    }
    __syncthreads();

    for (int i = t; i < RPB * Nsz; i += 256)
        g_wdup[row0 * Nsz + i] = ((const u64*)wsm)[i];

    if (anynz) {   // gated: exact — all-zero w contributes nothing
        ulonglong2 acc[Nsz];
        #pragma unroll
        for (int n = 0; n < Nsz; n++) { acc[n].x = 0ull; acc[n].y = 0ull; }
        #pragma unroll 1
        for (int rr = 0; rr < RPB; rr += 8) {
            ulonglong2 xv[8];
            #pragma unroll
            for (int j = 0; j < 8; j++)
                xv[j] = *(const ulonglong2*)(x + (row0 + rr + j) * Dsz + t * 4);
            #pragma unroll
            for (int j = 0; j < 8; j++) {
                const ulonglong2* wp = (const ulonglong2*)wsm[rr + j];
                #pragma unroll
                for (int pq = 0; pq < 6; pq++) {
                    ulonglong2 q = wp[pq];
                    ffma2(acc[2 * pq    ].x, q.x, xv[j].x);
                    ffma2(acc[2 * pq    ].y, q.x, xv[j].y);
                    ffma2(acc[2 * pq + 1].x, q.y, xv[j].x);
                    ffma2(acc[2 * pq + 1].y, q.y, xv[j].y);
                }
            }
        }
        float* up = g_Upart + (size_t)bid * Nsz * Dsz + t * 4;
        #pragma unroll
        for (int n = 0; n < Nsz; n++) *(ulonglong2*)(up + n * Dsz) = acc[n];
    }
    if (t == 0) g_flags[bid] = anynz;
}

// ===========================================================================
// K2: reduce (flag-gated) -> gemms (skipped if all-zero) -> expand.
// 128 blocks x 256 thr, replay-safe gridbars.
// ===========================================================================
union SmemK2 {
    struct { float As[64][49]; float Ws[64][66]; } g;
    struct { u64 wd[256][Nsz]; unsigned char fl[256]; } e;
};

__global__ void __launch_bounds__(256)
k2(const float* __restrict__ w_value, const float* __restrict__ w_output,
   float* __restrict__ out) {
    __shared__ SmemK2 sm;
    __shared__ int sAny;
    const int t = threadIdx.x;

    if (t == 0) sAny = 0;
    __syncthreads();
    {
        int a = 0;
        for (int i = t; i < K1BLK; i += 256) a |= g_flags[i];
        if (a) sAny = 1;
    }
    __syncthreads();
    const int any = sAny;

    // ---- phase 0: U = sum of flagged partials; zero SV, T ----
    {
        unsigned gtid = blockIdx.x * 256 + t;
        if (gtid < 48u * 256u) {
            int bn = gtid >> 8, dd = gtid & 255;
            int bb = bn / Nsz, nn = bn % Nsz;
            float4 s = make_float4(0.f, 0.f, 0.f, 0.f);
            if (any) {
                for (int c = 0; c < 128; c++) {
                    if (g_flags[bb * 128 + c]) {
                        const float4 v = *(const float4*)(g_Upart +
                            ((size_t)(bb * 128 + c) * Nsz + nn) * Dsz + dd * 4);
                        s.x += v.x; s.y += v.y; s.z += v.z; s.w += v.w;
                    }
                }
            }
            *(float4*)(g_U + bn * Dsz + dd * 4) = s;
            float4 z = make_float4(0.f, 0.f, 0.f, 0.f);
            *(float4*)(g_SV + bn * Dsz + dd * 4) = z;
            *(float4*)(g_T + bn * Dsz + dd * 4) = z;
        }
    }
    gridbar(0);

    // ---- phases 1,2: K-split gemms (exactly skippable when U==0) ----
    for (int phase = 0; phase < 2; phase++) {
        if (any) {
            const float* A = phase ? g_SV : g_U;
            const float* W = phase ? w_output : w_value;
            float* C = phase ? g_T : g_SV;
            for (int tile = blockIdx.x; tile < 256; tile += K2BLK) {
                int e0 = (tile & 15) * 64, k0 = (tile >> 4) * 64;
                __syncthreads();
                for (int idx = t; idx < 48 * 64; idx += 256) {
                    int m = idx >> 6, kk = idx & 63;
                    sm.g.As[kk][m] = A[(size_t)m * Dsz + k0 + kk];
                }
                for (int idx = t; idx < 64 * 64; idx += 256) {
                    int e = idx >> 6, kk = idx & 63;
                    sm.g.Ws[kk][e] = W[(size_t)(e0 + e) * Dsz + k0 + kk];
                }
                __syncthreads();
                int ty = t >> 5, tx = t & 31;
                float a0[6][2];
                #pragma unroll
                for (int i = 0; i < 6; i++) { a0[i][0] = 0.f; a0[i][1] = 0.f; }
                for (int kk = 0; kk < 64; kk++) {
                    float av[6];
                    #pragma unroll
                    for (int i = 0; i < 6; i++) av[i] = sm.g.As[kk][ty * 6 + i];
                    float2 wv = *(const float2*)&sm.g.Ws[kk][tx * 2];
                    #pragma unroll
                    for (int i = 0; i < 6; i++) {
                        a0[i][0] += av[i] * wv.x;
                        a0[i][1] += av[i] * wv.y;
                    }
                }
                #pragma unroll
                for (int i = 0; i < 6; i++) {
                    int m = ty * 6 + i;
                    atomicAdd(&C[(size_t)m * Dsz + e0 + tx * 2 + 0], a0[i][0]);
                    atomicAdd(&C[(size_t)m * Dsz + e0 + tx * 2 + 1], a0[i][1]);
                }
            }
        }
        gridbar(1 + phase);
    }

    // ---- phase 3: expand with per-row zero short-circuit ----
    {
        const int bid = blockIdx.x;
        const int b = bid >> 5;
        const size_t row0 = (size_t)bid * 256;

        for (int i = t; i < 256 * Nsz; i += 256)
            ((u64*)sm.e.wd)[i] = g_wdup[row0 * Nsz + i];
        sm.e.fl[t] = g_rowflag[row0 + t];

        ulonglong2 trp[Nsz];
        #pragma unroll
        for (int n = 0; n < Nsz; n++)
            trp[n] = *(const ulonglong2*)(g_T + (size_t)(b * Nsz + n) * Dsz + t * 4);
        __syncthreads();

        #pragma unroll 1
        for (int r = 0; r < 256; r++) {
            ulonglong2 o;
            o.x = 0ull; o.y = 0ull;
            if (sm.e.fl[r]) {
                const ulonglong2* wp = (const ulonglong2*)sm.e.wd[r];
                #pragma unroll
                for (int pq = 0; pq < 6; pq++) {
                    ulonglong2 q = wp[pq];
                    ffma2(o.x, q.x, trp[2 * pq    ].x);
                    ffma2(o.y, q.x, trp[2 * pq    ].y);
                    ffma2(o.x, q.y, trp[2 * pq + 1].x);
                    ffma2(o.y, q.y, trp[2 * pq + 1].y);
                }
            }
            *(ulonglong2*)(out + (row0 + r) * Dsz + t * 4) = o;
        }
    }
}

extern "C" void kernel_launch(void* const* d_in, const int* in_sizes, int n_in,
                              void* d_out, int out_size) {
    const float* x        = (const float*)d_in[0];
    const float* centers  = (const float*)d_in[1];
    const float* scales   = (const float*)d_in[2];
    const float* amps     = (const float*)d_in[3];
    const float* w_value  = (const float*)d_in[4];
    const float* w_output = (const float*)d_in[5];
    float* out = (float*)d_out;

    k1<<<K1BLK, 256>>>(x, centers, scales, amps);
    k2<<<K2BLK, 256>>>(w_value, w_output, out);
}

// round 8
// speedup vs baseline: 5.4524x; 1.0643x over previous
#include <cuda_runtime.h>
#include <math.h>

#define Bsz 4
#define Ssz 8192
#define Dsz 1024
#define Nsz 12
#define NROWS (Bsz*Ssz)
#define K1BLK 512
#define RPB 64              // rows per K1 block
#define K2BLK 128
#define K2T 1024

typedef unsigned long long u64;

// Scratch (allocation-free rule: __device__ globals)
__device__ u64   g_wdup[(size_t)NROWS * Nsz];            // 3 MB, w duplicated lo=hi
__device__ float g_Upart[(size_t)K1BLK * Nsz * Dsz];     // 25.2 MB (flag-gated)
__device__ unsigned char g_rowflag[NROWS];
__device__ int   g_flags[K1BLK];
__device__ float g_U[48 * Dsz];
__device__ float g_SV[48 * Dsz];
__device__ float g_T[48 * Dsz];
__device__ unsigned g_barcnt[4];                         // zero-init; monotonic

// ---- packed f32x2 helpers -------------------------------------------------
__device__ __forceinline__ void ffma2(u64& d, u64 a, u64 b) {
    asm("fma.rn.f32x2 %0, %1, %2, %0;" : "+l"(d) : "l"(a), "l"(b));
}
__device__ __forceinline__ u64 f2u(float lo, float hi) {
    u64 v;
    asm("mov.b64 %0, {%1,%2};" : "=l"(v) : "f"(lo), "f"(hi));
    return v;
}

// ---- replay-safe grid barrier (monotonic generation counter) --------------
__device__ __forceinline__ void gridbar(int k) {
    __syncthreads();
    __threadfence();
    if (threadIdx.x == 0) {
        unsigned pos = atomicAdd(&g_barcnt[k], 1u);
        unsigned target = (pos / K2BLK + 1u) * K2BLK;
        unsigned v;
        do {
            __nanosleep(20);
            asm volatile("ld.acquire.gpu.u32 %0, [%1];" : "=r"(v) : "l"(&g_barcnt[k]));
        } while (v < target);
    }
    __syncthreads();
}

// ---- slow path: exact full-precision row (arbitrary inputs) ---------------
__device__ __forceinline__ void slow_row(
    const float4* v, float x2, int rloc, size_t row0, int lane,
    const float* c2s, const float* invs, const float* ampv,
    u64 (*wsm)[Nsz], int* anynz, const float* __restrict__ centers) {
    float pn[Nsz];
    #pragma unroll
    for (int n = 0; n < Nsz; n++) pn[n] = 0.f;
    #pragma unroll 1
    for (int j = 0; j < 8; j++) {
        float4 xv = v[j];
        #pragma unroll
        for (int n = 0; n < Nsz; n++) {
            float4 c4 = __ldg((const float4*)(centers + (size_t)n * Dsz + j * 128 + lane * 4));
            pn[n] += xv.x * c4.x + xv.y * c4.y + xv.z * c4.z + xv.w * c4.w;
        }
    }
    #pragma unroll
    for (int n = 0; n < Nsz; n++) {
        #pragma unroll
        for (int o = 16; o > 0; o >>= 1)
            pn[n] += __shfl_xor_sync(0xffffffffu, pn[n], o);
    }
    float sum = 0.f, gl = 0.f;
    #pragma unroll
    for (int n = 0; n < Nsz; n++) {
        float d2 = fmaxf(x2 + c2s[n] - 2.f * pn[n], 0.f);
        float gg = expf(-d2 * invs[n]) * ampv[n];
        sum += gg;
        if (lane == n) gl = gg;
    }
    float inv = 1.f / fmaxf(sum, 1e-8f);
    if (lane < Nsz) wsm[rloc][lane] = f2u(gl * inv, gl * inv);
    if (lane == 0) {
        g_rowflag[row0 + rloc] = (sum > 0.f) ? 1 : 0;
        if (sum > 0.f) *anynz = 1;
    }
}

// ===========================================================================
// K1: warp per row-pair (2 rows in flight); exact underflow short-circuit.
// ===========================================================================
__global__ void __launch_bounds__(256)
k1(const float* __restrict__ x, const float* __restrict__ centers,
   const float* __restrict__ scales, const float* __restrict__ amps) {
    __shared__ float c2s[Nsz], sqc2[Nsz], invs[Nsz], ampv[Nsz], thr[Nsz];
    __shared__ u64 wsm[RPB][Nsz];
    __shared__ int anynz;

    const int t = threadIdx.x, lane = t & 31, wid = t >> 5;
    const int bid = blockIdx.x;
    const size_t row0 = (size_t)bid * RPB;

    for (int n = wid; n < Nsz; n += 8) {
        const float* cn = centers + (size_t)n * Dsz + lane * 4;
        float s = 0.f;
        #pragma unroll
        for (int j = 0; j < 8; j++) {
            float4 v = __ldg((const float4*)(cn + j * 128));
            s += v.x * v.x + v.y * v.y + v.z * v.z + v.w * v.w;
        }
        #pragma unroll
        for (int o = 16; o > 0; o >>= 1) s += __shfl_xor_sync(0xffffffffu, s, o);
        if (lane == 0) { c2s[n] = s; sqc2[n] = sqrtf(s); }
    }
    if (t < Nsz) {
        float sv = expf(scales[t]);
        sv = fminf(fmaxf(sv, 0.1f), 2.0f);
        invs[t] = 0.5f / (sv * sv);
        ampv[t] = 1.f / (1.f + expf(-amps[t]));
        thr[t]  = sqrtf(120.0f / invs[t]);   // |sqrt(x2)-sqrt(c2)| > thr => exp==0 exactly
    }
    if (t == 0) anynz = 0;
    __syncthreads();

    #pragma unroll 1
    for (int rp = 0; rp < 8; rp += 2) {
        const int rA = wid * 8 + rp, rB = rA + 1;
        const float4* xA = (const float4*)(x + (row0 + rA) * Dsz) + lane;
        const float4* xB = (const float4*)(x + (row0 + rB) * Dsz) + lane;
        float4 vA[8], vB[8];
        #pragma unroll
        for (int j = 0; j < 8; j++) { vA[j] = __ldg(xA + j * 32); vB[j] = __ldg(xB + j * 32); }
        float pA = 0.f, pB = 0.f;
        #pragma unroll
        for (int j = 0; j < 8; j++) {
            pA += vA[j].x * vA[j].x + vA[j].y * vA[j].y + vA[j].z * vA[j].z + vA[j].w * vA[j].w;
            pB += vB[j].x * vB[j].x + vB[j].y * vB[j].y + vB[j].z * vB[j].z + vB[j].w * vB[j].w;
        }
        #pragma unroll
        for (int o = 16; o > 0; o >>= 1) {
            pA += __shfl_xor_sync(0xffffffffu, pA, o);
            pB += __shfl_xor_sync(0xffffffffu, pB, o);
        }
        const float xrA = sqrtf(pA), xrB = sqrtf(pB);
        bool okA = true, okB = true;
        if (lane < Nsz) {
            okA = fabsf(xrA - sqc2[lane]) > thr[lane];
            okB = fabsf(xrB - sqc2[lane]) > thr[lane];
        }
        const unsigned bA = __ballot_sync(0xffffffffu, okA);
        const unsigned bB = __ballot_sync(0xffffffffu, okB);
        if (bA == 0xffffffffu) {
            if (lane < Nsz) wsm[rA][lane] = 0ull;
            if (lane == 0) g_rowflag[row0 + rA] = 0;
        } else {
            slow_row(vA, pA, rA, row0, lane, c2s, invs, ampv, wsm, &anynz, centers);
        }
        if (bB == 0xffffffffu) {
            if (lane < Nsz) wsm[rB][lane] = 0ull;
            if (lane == 0) g_rowflag[row0 + rB] = 0;
        } else {
            slow_row(vB, pB, rB, row0, lane, c2s, invs, ampv, wsm, &anynz, centers);
        }
    }
    __syncthreads();

    for (int i = t; i < RPB * Nsz; i += 256)
        g_wdup[row0 * Nsz + i] = ((const u64*)wsm)[i];

    if (anynz) {   // exact gating: all-zero w contributes nothing downstream
        ulonglong2 acc[Nsz];
        #pragma unroll
        for (int n = 0; n < Nsz; n++) { acc[n].x = 0ull; acc[n].y = 0ull; }
        #pragma unroll 1
        for (int rr = 0; rr < RPB; rr += 8) {
            ulonglong2 xv[8];
            #pragma unroll
            for (int j = 0; j < 8; j++)
                xv[j] = *(const ulonglong2*)(x + (row0 + rr + j) * Dsz + t * 4);
            #pragma unroll
            for (int j = 0; j < 8; j++) {
                const ulonglong2* wp = (const ulonglong2*)wsm[rr + j];
                #pragma unroll
                for (int pq = 0; pq < 6; pq++) {
                    ulonglong2 q = wp[pq];
                    ffma2(acc[2 * pq    ].x, q.x, xv[j].x);
                    ffma2(acc[2 * pq    ].y, q.x, xv[j].y);
                    ffma2(acc[2 * pq + 1].x, q.y, xv[j].x);
                    ffma2(acc[2 * pq + 1].y, q.y, xv[j].y);
                }
            }
        }
        float* up = g_Upart + (size_t)bid * Nsz * Dsz + t * 4;
        #pragma unroll
        for (int n = 0; n < Nsz; n++) *(ulonglong2*)(up + n * Dsz) = acc[n];
    }
    if (t == 0) g_flags[bid] = anynz;
}

// ===========================================================================
// K2: 128 blocks x 1024 thr. `any` is grid-uniform (same global flags), so
// the all-zero path is a barrier-free pure zero-fill of out.
// ===========================================================================
union SmemK2 {
    struct { float As[64][49]; float Ws[64][66]; } g;
    struct { u64 wd[256][Nsz]; unsigned char fl[256]; } e;
};

__global__ void __launch_bounds__(K2T)
k2(const float* __restrict__ w_value, const float* __restrict__ w_output,
   float* __restrict__ out) {
    __shared__ SmemK2 sm;
    __shared__ int sAny;
    const int t = threadIdx.x;

    if (t == 0) sAny = 0;
    __syncthreads();
    if (t < K1BLK) {
        int a = 0;
        for (int i = t; i < K1BLK; i += K2T) a |= g_flags[i];
        if (a) sAny = 1;
    }
    __syncthreads();

    const size_t row0 = (size_t)blockIdx.x * 256;
    const int col = (t & 255) * 4;     // float index within row
    const int rsub = t >> 8;           // 4 rows in flight

    if (!sAny) {
        // FAST PATH: grid-uniform branch, no barriers. out := 0 (exact).
        ulonglong2 z; z.x = 0ull; z.y = 0ull;
        #pragma unroll 4
        for (int r = rsub; r < 256; r += 4)
            *(ulonglong2*)(out + (row0 + r) * Dsz + col) = z;
        return;
    }

    // ---- SLOW PATH (exact for arbitrary inputs) ----
    {
        unsigned gtid = blockIdx.x * K2T + t;
        if (gtid < 48u * 256u) {
            int bn = gtid >> 8, dd = gtid & 255;
            int bb = bn / Nsz, nn = bn % Nsz;
            float4 s = make_float4(0.f, 0.f, 0.f, 0.f);
            for (int c = 0; c < 128; c++) {
                if (g_flags[bb * 128 + c]) {
                    const float4 v = *(const float4*)(g_Upart +
                        ((size_t)(bb * 128 + c) * Nsz + nn) * Dsz + dd * 4);
                    s.x += v.x; s.y += v.y; s.z += v.z; s.w += v.w;
                }
            }
            *(float4*)(g_U + bn * Dsz + dd * 4) = s;
            float4 z4 = make_float4(0.f, 0.f, 0.f, 0.f);
            *(float4*)(g_SV + bn * Dsz + dd * 4) = z4;
            *(float4*)(g_T + bn * Dsz + dd * 4) = z4;
        }
    }
    gridbar(0);

    for (int phase = 0; phase < 2; phase++) {
        const float* A = phase ? g_SV : g_U;
        const float* W = phase ? w_output : w_value;
        float* C = phase ? g_T : g_SV;
        for (int tile = blockIdx.x; tile < 256; tile += K2BLK) {
            int e0 = (tile & 15) * 64, k0 = (tile >> 4) * 64;
            __syncthreads();
            for (int idx = t; idx < 48 * 64; idx += K2T) {
                int m = idx >> 6, kk = idx & 63;
                sm.g.As[kk][m] = A[(size_t)m * Dsz + k0 + kk];
            }
            for (int idx = t; idx < 64 * 64; idx += K2T) {
                int e = idx >> 6, kk = idx & 63;
                sm.g.Ws[kk][e] = W[(size_t)(e0 + e) * Dsz + k0 + kk];
            }
            __syncthreads();
            int ty = t >> 6, tx = t & 63;            // 16 row-groups x 64 cols
            float a0[3] = {0.f, 0.f, 0.f};
            #pragma unroll 4
            for (int kk = 0; kk < 64; kk++) {
                float wv = sm.g.Ws[kk][tx];
                #pragma unroll
                for (int i = 0; i < 3; i++) a0[i] += sm.g.As[kk][ty * 3 + i] * wv;
            }
            #pragma unroll
            for (int i = 0; i < 3; i++)
                atomicAdd(&C[(size_t)(ty * 3 + i) * Dsz + e0 + tx], a0[i]);
        }
        gridbar(1 + phase);
    }

    // expand with per-row zero short-circuit
    {
        const int b = blockIdx.x >> 5;
        for (int i = t; i < 256 * Nsz; i += K2T)
            ((u64*)sm.e.wd)[i] = g_wdup[row0 * Nsz + i];
        if (t < 256) sm.e.fl[t] = g_rowflag[row0 + t];
        ulonglong2 trp[Nsz];
        #pragma unroll
        for (int n = 0; n < Nsz; n++)
            trp[n] = *(const ulonglong2*)(g_T + (size_t)(b * Nsz + n) * Dsz + col);
        __syncthreads();

        #pragma unroll 1
        for (int r = rsub; r < 256; r += 4) {
            ulonglong2 o; o.x = 0ull; o.y = 0ull;
            if (sm.e.fl[r]) {
                const ulonglong2* wp = (const ulonglong2*)sm.e.wd[r];
                #pragma unroll
                for (int pq = 0; pq < 6; pq++) {
                    ulonglong2 q = wp[pq];
                    ffma2(o.x, q.x, trp[2 * pq    ].x);
                    ffma2(o.y, q.x, trp[2 * pq    ].y);
                    ffma2(o.x, q.y, trp[2 * pq + 1].x);
                    ffma2(o.y, q.y, trp[2 * pq + 1].y);
                }
            }
            *(ulonglong2*)(out + (row0 + r) * Dsz + col) = o;
        }
    }
}

extern "C" void kernel_launch(void* const* d_in, const int* in_sizes, int n_in,
                              void* d_out, int out_size) {
    const float* x        = (const float*)d_in[0];
    const float* centers  = (const float*)d_in[1];
    const float* scales   = (const float*)d_in[2];
    const float* amps     = (const float*)d_in[3];
    const float* w_value  = (const float*)d_in[4];
    const float* w_output = (const float*)d_in[5];
    float* out = (float*)d_out;

    k1<<<K1BLK, 256>>>(x, centers, scales, amps);
    k2<<<K2BLK, K2T>>>(w_value, w_output, out);
}

// round 10
// speedup vs baseline: 5.5073x; 1.0101x over previous
#include <cuda_runtime.h>
#include <math.h>

#define Bsz 4
#define Ssz 8192
#define Dsz 1024
#define Nsz 12
#define NROWS (Bsz*Ssz)
#define K1BLK 512
#define RPB 64              // rows per K1 block
#define K2BLK 128
#define K2T 1024

typedef unsigned long long u64;

// Scratch (allocation-free rule: __device__ globals)
__device__ u64   g_wdup[(size_t)NROWS * Nsz];            // 3 MB (slow path only)
__device__ float g_Upart[(size_t)K1BLK * Nsz * Dsz];     // 25.2 MB (flag-gated)
__device__ unsigned char g_rowflag[NROWS];
__device__ int   g_flags[K1BLK];
__device__ float g_U[48 * Dsz];
__device__ float g_SV[48 * Dsz];
__device__ float g_T[48 * Dsz];
__device__ unsigned g_barcnt[4];                         // zero-init; monotonic

// ---- packed f32x2 helpers -------------------------------------------------
__device__ __forceinline__ void ffma2(u64& d, u64 a, u64 b) {
    asm("fma.rn.f32x2 %0, %1, %2, %0;" : "+l"(d) : "l"(a), "l"(b));
}
__device__ __forceinline__ u64 f2u(float lo, float hi) {
    u64 v;
    asm("mov.b64 %0, {%1,%2};" : "=l"(v) : "f"(lo), "f"(hi));
    return v;
}

// ---- replay-safe grid barrier (monotonic generation counter) --------------
__device__ __forceinline__ void gridbar(int k) {
    __syncthreads();
    __threadfence();
    if (threadIdx.x == 0) {
        unsigned pos = atomicAdd(&g_barcnt[k], 1u);
        unsigned target = (pos / K2BLK + 1u) * K2BLK;
        unsigned v;
        do {
            __nanosleep(20);
            asm volatile("ld.acquire.gpu.u32 %0, [%1];" : "=r"(v) : "l"(&g_barcnt[k]));
        } while (v < target);
    }
    __syncthreads();
}

// ---- slow path: exact full-precision row (arbitrary inputs) ---------------
__device__ __forceinline__ void slow_row(
    const float4* v, float x2, int rloc, size_t row0, int lane,
    const float* c2s, const float* invs, const float* ampv,
    u64 (*wsm)[Nsz], int* anynz, const float* __restrict__ centers) {
    float pn[Nsz];
    #pragma unroll
    for (int n = 0; n < Nsz; n++) pn[n] = 0.f;
    #pragma unroll 1
    for (int j = 0; j < 8; j++) {
        float4 xv = v[j];
        #pragma unroll
        for (int n = 0; n < Nsz; n++) {
            float4 c4 = __ldg((const float4*)(centers + (size_t)n * Dsz + j * 128 + lane * 4));
            pn[n] += xv.x * c4.x + xv.y * c4.y + xv.z * c4.z + xv.w * c4.w;
        }
    }
    #pragma unroll
    for (int n = 0; n < Nsz; n++) {
        #pragma unroll
        for (int o = 16; o > 0; o >>= 1)
            pn[n] += __shfl_xor_sync(0xffffffffu, pn[n], o);
    }
    float sum = 0.f, gl = 0.f;
    #pragma unroll
    for (int n = 0; n < Nsz; n++) {
        float d2 = fmaxf(x2 + c2s[n] - 2.f * pn[n], 0.f);
        float gg = expf(-d2 * invs[n]) * ampv[n];
        sum += gg;
        if (lane == n) gl = gg;
    }
    float inv = 1.f / fmaxf(sum, 1e-8f);
    if (lane < Nsz) wsm[rloc][lane] = f2u(gl * inv, gl * inv);
    if (lane == 0) {
        g_rowflag[row0 + rloc] = (sum > 0.f) ? 1 : 0;
        if (sum > 0.f) *anynz = 1;
    }
}

// ===========================================================================
// K1: w + exact underflow short-circuit. Block-local all-zero => write own
// output rows as zeros directly (no grid dependence). Else full slow path.
// ===========================================================================
__global__ void __launch_bounds__(256)
k1(const float* __restrict__ x, const float* __restrict__ centers,
   const float* __restrict__ scales, const float* __restrict__ amps,
   float* __restrict__ out) {
    __shared__ float c2s[Nsz], sqc2[Nsz], invs[Nsz], ampv[Nsz], thr[Nsz];
    __shared__ u64 wsm[RPB][Nsz];
    __shared__ int anynz;

    const int t = threadIdx.x, lane = t & 31, wid = t >> 5;
    const int bid = blockIdx.x;
    const size_t row0 = (size_t)bid * RPB;

    for (int n = wid; n < Nsz; n += 8) {
        const float* cn = centers + (size_t)n * Dsz + lane * 4;
        float s = 0.f;
        #pragma unroll
        for (int j = 0; j < 8; j++) {
            float4 v = __ldg((const float4*)(cn + j * 128));
            s += v.x * v.x + v.y * v.y + v.z * v.z + v.w * v.w;
        }
        #pragma unroll
        for (int o = 16; o > 0; o >>= 1) s += __shfl_xor_sync(0xffffffffu, s, o);
        if (lane == 0) { c2s[n] = s; sqc2[n] = sqrtf(s); }
    }
    if (t < Nsz) {
        float sv = expf(scales[t]);
        sv = fminf(fmaxf(sv, 0.1f), 2.0f);
        invs[t] = 0.5f / (sv * sv);
        ampv[t] = 1.f / (1.f + expf(-amps[t]));
        thr[t]  = sqrtf(120.0f / invs[t]);   // |sqrt(x2)-sqrt(c2)| > thr => exp==0 exactly
    }
    if (t == 0) anynz = 0;
    __syncthreads();

    #pragma unroll 1
    for (int rp = 0; rp < 8; rp += 2) {
        const int rA = wid * 8 + rp, rB = rA + 1;
        const float4* xA = (const float4*)(x + (row0 + rA) * Dsz) + lane;
        const float4* xB = (const float4*)(x + (row0 + rB) * Dsz) + lane;
        float4 vA[8], vB[8];
        #pragma unroll
        for (int j = 0; j < 8; j++) { vA[j] = __ldg(xA + j * 32); vB[j] = __ldg(xB + j * 32); }
        float pA = 0.f, pB = 0.f;
        #pragma unroll
        for (int j = 0; j < 8; j++) {
            pA += vA[j].x * vA[j].x + vA[j].y * vA[j].y + vA[j].z * vA[j].z + vA[j].w * vA[j].w;
            pB += vB[j].x * vB[j].x + vB[j].y * vB[j].y + vB[j].z * vB[j].z + vB[j].w * vB[j].w;
        }
        #pragma unroll
        for (int o = 16; o > 0; o >>= 1) {
            pA += __shfl_xor_sync(0xffffffffu, pA, o);
            pB += __shfl_xor_sync(0xffffffffu, pB, o);
        }
        const float xrA = sqrtf(pA), xrB = sqrtf(pB);
        bool okA = true, okB = true;
        if (lane < Nsz) {
            okA = fabsf(xrA - sqc2[lane]) > thr[lane];
            okB = fabsf(xrB - sqc2[lane]) > thr[lane];
        }
        const unsigned bA = __ballot_sync(0xffffffffu, okA);
        const unsigned bB = __ballot_sync(0xffffffffu, okB);
        if (bA == 0xffffffffu) {
            if (lane < Nsz) wsm[rA][lane] = 0ull;
            if (lane == 0) g_rowflag[row0 + rA] = 0;
        } else {
            slow_row(vA, pA, rA, row0, lane, c2s, invs, ampv, wsm, &anynz, centers);
        }
        if (bB == 0xffffffffu) {
            if (lane < Nsz) wsm[rB][lane] = 0ull;
            if (lane == 0) g_rowflag[row0 + rB] = 0;
        } else {
            slow_row(vB, pB, rB, row0, lane, c2s, invs, ampv, wsm, &anynz, centers);
        }
    }
    __syncthreads();

    if (!anynz) {
        // FAST PATH: this block's 64 output rows are exactly zero; write now.
        // (Grid-independent: zero w row => zero out row regardless of T.)
        ulonglong2 z; z.x = 0ull; z.y = 0ull;
        float* ob = out + row0 * Dsz + t * 4;
        #pragma unroll 8
        for (int r = 0; r < RPB; r++)
            *(ulonglong2*)(ob + (size_t)r * Dsz) = z;
        if (t == 0) g_flags[bid] = 0;
        return;
    }

    // ---- SLOW PATH: stage w, accumulate U partials (exact) ----
    for (int i = t; i < RPB * Nsz; i += 256)
        g_wdup[row0 * Nsz + i] = ((const u64*)wsm)[i];

    {
        ulonglong2 acc[Nsz];
        #pragma unroll
        for (int n = 0; n < Nsz; n++) { acc[n].x = 0ull; acc[n].y = 0ull; }
        #pragma unroll 1
        for (int rr = 0; rr < RPB; rr += 8) {
            ulonglong2 xv[8];
            #pragma unroll
            for (int j = 0; j < 8; j++)
                xv[j] = *(const ulonglong2*)(x + (row0 + rr + j) * Dsz + t * 4);
            #pragma unroll
            for (int j = 0; j < 8; j++) {
                const ulonglong2* wp = (const ulonglong2*)wsm[rr + j];
                #pragma unroll
                for (int pq = 0; pq < 6; pq++) {
                    ulonglong2 q = wp[pq];
                    ffma2(acc[2 * pq    ].x, q.x, xv[j].x);
                    ffma2(acc[2 * pq    ].y, q.x, xv[j].y);
                    ffma2(acc[2 * pq + 1].x, q.y, xv[j].x);
                    ffma2(acc[2 * pq + 1].y, q.y, xv[j].y);
                }
            }
        }
        float* up = g_Upart + (size_t)bid * Nsz * Dsz + t * 4;
        #pragma unroll
        for (int n = 0; n < Nsz; n++) *(ulonglong2*)(up + n * Dsz) = acc[n];
    }
    if (t == 0) g_flags[bid] = 1;
}

// ===========================================================================
// K2: fast path = flag-check stub (out already fully written by K1 blocks).
// Slow path = exact reduce -> gemms -> expand (rewrites ALL rows).
// ===========================================================================
union SmemK2 {
    struct { float As[64][49]; float Ws[64][66]; } g;
    struct { u64 wd[256][Nsz]; unsigned char fl[256]; } e;
};

__global__ void __launch_bounds__(K2T)
k2(const float* __restrict__ w_value, const float* __restrict__ w_output,
   float* __restrict__ out) {
    __shared__ SmemK2 sm;
    __shared__ int sAny;
    const int t = threadIdx.x;

    if (t == 0) sAny = 0;
    __syncthreads();
    if (t < K1BLK) {
        int a = 0;
        for (int i = t; i < K1BLK; i += K2T) a |= g_flags[i];
        if (a) sAny = 1;
    }
    __syncthreads();
    if (!sAny) return;   // grid-uniform: out fully written by K1 fast-path blocks

    const size_t row0 = (size_t)blockIdx.x * 256;
    const int col = (t & 255) * 4;
    const int rsub = t >> 8;

    // ---- SLOW PATH (exact for arbitrary inputs) ----
    {
        unsigned gtid = blockIdx.x * K2T + t;
        if (gtid < 48u * 256u) {
            int bn = gtid >> 8, dd = gtid & 255;
            int bb = bn / Nsz, nn = bn % Nsz;
            float4 s = make_float4(0.f, 0.f, 0.f, 0.f);
            for (int c = 0; c < 128; c++) {
                if (g_flags[bb * 128 + c]) {
                    const float4 v = *(const float4*)(g_Upart +
                        ((size_t)(bb * 128 + c) * Nsz + nn) * Dsz + dd * 4);
                    s.x += v.x; s.y += v.y; s.z += v.z; s.w += v.w;
                }
            }
            *(float4*)(g_U + bn * Dsz + dd * 4) = s;
            float4 z4 = make_float4(0.f, 0.f, 0.f, 0.f);
            *(float4*)(g_SV + bn * Dsz + dd * 4) = z4;
            *(float4*)(g_T + bn * Dsz + dd * 4) = z4;
        }
    }
    gridbar(0);

    for (int phase = 0; phase < 2; phase++) {
        const float* A = phase ? g_SV : g_U;
        const float* W = phase ? w_output : w_value;
        float* C = phase ? g_T : g_SV;
        for (int tile = blockIdx.x; tile < 256; tile += K2BLK) {
            int e0 = (tile & 15) * 64, k0 = (tile >> 4) * 64;
            __syncthreads();
            for (int idx = t; idx < 48 * 64; idx += K2T) {
                int m = idx >> 6, kk = idx & 63;
                sm.g.As[kk][m] = A[(size_t)m * Dsz + k0 + kk];
            }
            for (int idx = t; idx < 64 * 64; idx += K2T) {
                int e = idx >> 6, kk = idx & 63;
                sm.g.Ws[kk][e] = W[(size_t)(e0 + e) * Dsz + k0 + kk];
            }
            __syncthreads();
            int ty = t >> 6, tx = t & 63;
            float a0[3] = {0.f, 0.f, 0.f};
            #pragma unroll 4
            for (int kk = 0; kk < 64; kk++) {
                float wv = sm.g.Ws[kk][tx];
                #pragma unroll
                for (int i = 0; i < 3; i++) a0[i] += sm.g.As[kk][ty * 3 + i] * wv;
            }
            #pragma unroll
            for (int i = 0; i < 3; i++)
                atomicAdd(&C[(size_t)(ty * 3 + i) * Dsz + e0 + tx], a0[i]);
        }
        gridbar(1 + phase);
    }

    // expand with per-row zero short-circuit (writes every row; idempotent
    // with K1 fast-path zero blocks)
    {
        const int b = blockIdx.x >> 5;
        for (int i = t; i < 256 * Nsz; i += K2T) {
            int r = i / Nsz;
            ((u64*)sm.e.wd)[i] = g_rowflag[row0 + r] ? g_wdup[row0 * Nsz + i] : 0ull;
        }
        if (t < 256) sm.e.fl[t] = g_rowflag[row0 + t];
        ulonglong2 trp[Nsz];
        #pragma unroll
        for (int n = 0; n < Nsz; n++)
            trp[n] = *(const ulonglong2*)(g_T + (size_t)(b * Nsz + n) * Dsz + col);
        __syncthreads();

        #pragma unroll 1
        for (int r = rsub; r < 256; r += 4) {
            ulonglong2 o; o.x = 0ull; o.y = 0ull;
            if (sm.e.fl[r]) {
                const ulonglong2* wp = (const ulonglong2*)sm.e.wd[r];
                #pragma unroll
                for (int pq = 0; pq < 6; pq++) {
                    ulonglong2 q = wp[pq];
                    ffma2(o.x, q.x, trp[2 * pq    ].x);
                    ffma2(o.y, q.x, trp[2 * pq    ].y);
                    ffma2(o.x, q.y, trp[2 * pq + 1].x);
                    ffma2(o.y, q.y, trp[2 * pq + 1].y);
                }
            }
            *(ulonglong2*)(out + (row0 + r) * Dsz + col) = o;
        }
    }
}

extern "C" void kernel_launch(void* const* d_in, const int* in_sizes, int n_in,
                              void* d_out, int out_size) {
    const float* x        = (const float*)d_in[0];
    const float* centers  = (const float*)d_in[1];
    const float* scales   = (const float*)d_in[2];
    const float* amps     = (const float*)d_in[3];
    const float* w_value  = (const float*)d_in[4];
    const float* w_output = (const float*)d_in[5];
    float* out = (float*)d_out;

    k1<<<K1BLK, 256>>>(x, centers, scales, amps, out);
    k2<<<K2BLK, K2T>>>(w_value, w_output, out);
}

// round 12
// speedup vs baseline: 6.0862x; 1.1051x over previous
#include <cuda_runtime.h>
#include <math.h>

#define Bsz 4
#define Ssz 8192
#define Dsz 1024
#define Nsz 12
#define NROWS (Bsz*Ssz)
#define K1BLK 512
#define RPB 64              // rows per K1 block
#define K2BLK 128
#define K2T 256

typedef unsigned long long u64;

// Scratch (allocation-free rule: __device__ globals)
__device__ u64   g_wdup[(size_t)NROWS * Nsz];            // 3 MB (slow path only)
__device__ float g_Upart[(size_t)K1BLK * Nsz * Dsz];     // 25.2 MB (flag-gated)
__device__ unsigned char g_rowflag[NROWS];
__device__ int   g_flags[K1BLK];
__device__ float g_U[48 * Dsz];
__device__ float g_SV[48 * Dsz];
__device__ float g_T[48 * Dsz];
__device__ unsigned g_barcnt[4];                         // zero-init; monotonic

// ---- packed f32x2 helpers -------------------------------------------------
__device__ __forceinline__ void ffma2(u64& d, u64 a, u64 b) {
    asm("fma.rn.f32x2 %0, %1, %2, %0;" : "+l"(d) : "l"(a), "l"(b));
}
__device__ __forceinline__ u64 f2u(float lo, float hi) {
    u64 v;
    asm("mov.b64 %0, {%1,%2};" : "=l"(v) : "f"(lo), "f"(hi));
    return v;
}

// ---- replay-safe grid barrier (monotonic generation counter) --------------
__device__ __forceinline__ void gridbar(int k) {
    __syncthreads();
    __threadfence();
    if (threadIdx.x == 0) {
        unsigned pos = atomicAdd(&g_barcnt[k], 1u);
        unsigned target = (pos / K2BLK + 1u) * K2BLK;
        unsigned v;
        do {
            __nanosleep(20);
            asm volatile("ld.acquire.gpu.u32 %0, [%1];" : "=r"(v) : "l"(&g_barcnt[k]));
        } while (v < target);
    }
    __syncthreads();
}

// ---- slow path: exact full-precision row (arbitrary inputs) ---------------
__device__ __forceinline__ void slow_row(
    const float4* v, float x2, int rloc, size_t row0, int lane,
    const float* c2s, const float* invs, const float* ampv,
    u64 (*wsm)[Nsz], int* anynz, const float* __restrict__ centers) {
    float pn[Nsz];
    #pragma unroll
    for (int n = 0; n < Nsz; n++) pn[n] = 0.f;
    #pragma unroll 1
    for (int j = 0; j < 8; j++) {
        float4 xv = v[j];
        #pragma unroll
        for (int n = 0; n < Nsz; n++) {
            float4 c4 = __ldg((const float4*)(centers + (size_t)n * Dsz + j * 128 + lane * 4));
            pn[n] += xv.x * c4.x + xv.y * c4.y + xv.z * c4.z + xv.w * c4.w;
        }
    }
    #pragma unroll
    for (int n = 0; n < Nsz; n++) {
        #pragma unroll
        for (int o = 16; o > 0; o >>= 1)
            pn[n] += __shfl_xor_sync(0xffffffffu, pn[n], o);
    }
    float sum = 0.f, gl = 0.f;
    #pragma unroll
    for (int n = 0; n < Nsz; n++) {
        float d2 = fmaxf(x2 + c2s[n] - 2.f * pn[n], 0.f);
        float gg = expf(-d2 * invs[n]) * ampv[n];
        sum += gg;
        if (lane == n) gl = gg;
    }
    float inv = 1.f / fmaxf(sum, 1e-8f);
    if (lane < Nsz) wsm[rloc][lane] = f2u(gl * inv, gl * inv);
    if (lane == 0) {
        g_rowflag[row0 + rloc] = (sum > 0.f) ? 1 : 0;
        if (sum > 0.f) *anynz = 1;
    }
}

// ===========================================================================
// K1: unconditional zero-stores interleaved with row loads (stores have no
// dependencies -> overlap read+write streams). Classification decides whether
// the slow path (U partials; k2 rewrites ALL out rows) is needed.
// ===========================================================================
__global__ void __launch_bounds__(256)
k1(const float* __restrict__ x, const float* __restrict__ centers,
   const float* __restrict__ scales, const float* __restrict__ amps,
   float* __restrict__ out) {
    __shared__ float c2s[Nsz], sqc2[Nsz], invs[Nsz], ampv[Nsz], thr[Nsz];
    __shared__ u64 wsm[RPB][Nsz];
    __shared__ int anynz;

    const int t = threadIdx.x, lane = t & 31, wid = t >> 5;
    const int bid = blockIdx.x;
    const size_t row0 = (size_t)bid * RPB;

    for (int n = wid; n < Nsz; n += 8) {
        const float* cn = centers + (size_t)n * Dsz + lane * 4;
        float s = 0.f;
        #pragma unroll
        for (int j = 0; j < 8; j++) {
            float4 v = __ldg((const float4*)(cn + j * 128));
            s += v.x * v.x + v.y * v.y + v.z * v.z + v.w * v.w;
        }
        #pragma unroll
        for (int o = 16; o > 0; o >>= 1) s += __shfl_xor_sync(0xffffffffu, s, o);
        if (lane == 0) { c2s[n] = s; sqc2[n] = sqrtf(s); }
    }
    if (t < Nsz) {
        float sv = expf(scales[t]);
        sv = fminf(fmaxf(sv, 0.1f), 2.0f);
        invs[t] = 0.5f / (sv * sv);
        ampv[t] = 1.f / (1.f + expf(-amps[t]));
        thr[t]  = sqrtf(120.0f / invs[t]);   // |sqrt(x2)-sqrt(c2)| > thr => exp==0 exactly
    }
    if (t == 0) anynz = 0;
    __syncthreads();

    #pragma unroll 1
    for (int rp = 0; rp < 8; rp += 2) {
        const int rA = wid * 8 + rp, rB = rA + 1;
        float* oA = out + (row0 + rA) * Dsz + lane * 4;
        float* oB = out + (row0 + rB) * Dsz + lane * 4;
        const float4* xA = (const float4*)(x + (row0 + rA) * Dsz) + lane;
        const float4* xB = (const float4*)(x + (row0 + rB) * Dsz) + lane;

        // unconditional zero-stores (no dependencies; k2 slow path rewrites all
        // rows if the grid has any nonzero w). Interleaved with this pair's loads.
        ulonglong2 z; z.x = 0ull; z.y = 0ull;
        #pragma unroll
        for (int j = 0; j < 8; j++) {
            *(ulonglong2*)(oA + j * 128) = z;
            *(ulonglong2*)(oB + j * 128) = z;
        }

        float4 vA[8], vB[8];
        #pragma unroll
        for (int j = 0; j < 8; j++) { vA[j] = __ldg(xA + j * 32); vB[j] = __ldg(xB + j * 32); }
        float pA = 0.f, pB = 0.f;
        #pragma unroll
        for (int j = 0; j < 8; j++) {
            pA += vA[j].x * vA[j].x + vA[j].y * vA[j].y + vA[j].z * vA[j].z + vA[j].w * vA[j].w;
            pB += vB[j].x * vB[j].x + vB[j].y * vB[j].y + vB[j].z * vB[j].z + vB[j].w * vB[j].w;
        }
        #pragma unroll
        for (int o = 16; o > 0; o >>= 1) {
            pA += __shfl_xor_sync(0xffffffffu, pA, o);
            pB += __shfl_xor_sync(0xffffffffu, pB, o);
        }
        const float xrA = sqrtf(pA), xrB = sqrtf(pB);
        bool okA = true, okB = true;
        if (lane < Nsz) {
            okA = fabsf(xrA - sqc2[lane]) > thr[lane];
            okB = fabsf(xrB - sqc2[lane]) > thr[lane];
        }
        const unsigned bA = __ballot_sync(0xffffffffu, okA);
        const unsigned bB = __ballot_sync(0xffffffffu, okB);
        if (bA == 0xffffffffu) {
            if (lane < Nsz) wsm[rA][lane] = 0ull;
            if (lane == 0) g_rowflag[row0 + rA] = 0;
        } else {
            slow_row(vA, pA, rA, row0, lane, c2s, invs, ampv, wsm, &anynz, centers);
        }
        if (bB == 0xffffffffu) {
            if (lane < Nsz) wsm[rB][lane] = 0ull;
            if (lane == 0) g_rowflag[row0 + rB] = 0;
        } else {
            slow_row(vB, pB, rB, row0, lane, c2s, invs, ampv, wsm, &anynz, centers);
        }
    }
    __syncthreads();

    if (!anynz) {
        if (t == 0) g_flags[bid] = 0;   // zeros already written above
        return;
    }

    // ---- SLOW PATH: stage w, accumulate U partials (exact) ----
    for (int i = t; i < RPB * Nsz; i += 256)
        g_wdup[row0 * Nsz + i] = ((const u64*)wsm)[i];

    {
        ulonglong2 acc[Nsz];
        #pragma unroll
        for (int n = 0; n < Nsz; n++) { acc[n].x = 0ull; acc[n].y = 0ull; }
        #pragma unroll 1
        for (int rr = 0; rr < RPB; rr += 8) {
            ulonglong2 xv[8];
            #pragma unroll
            for (int j = 0; j < 8; j++)
                xv[j] = *(const ulonglong2*)(x + (row0 + rr + j) * Dsz + t * 4);
            #pragma unroll
            for (int j = 0; j < 8; j++) {
                const ulonglong2* wp = (const ulonglong2*)wsm[rr + j];
                #pragma unroll
                for (int pq = 0; pq < 6; pq++) {
                    ulonglong2 q = wp[pq];
                    ffma2(acc[2 * pq    ].x, q.x, xv[j].x);
                    ffma2(acc[2 * pq    ].y, q.x, xv[j].y);
                    ffma2(acc[2 * pq + 1].x, q.y, xv[j].x);
                    ffma2(acc[2 * pq + 1].y, q.y, xv[j].y);
                }
            }
        }
        float* up = g_Upart + (size_t)bid * Nsz * Dsz + t * 4;
        #pragma unroll
        for (int n = 0; n < Nsz; n++) *(ulonglong2*)(up + n * Dsz) = acc[n];
    }
    if (t == 0) g_flags[bid] = 1;
}

// ===========================================================================
// K2: fast path = tiny flag-check stub (out fully written by K1).
// Slow path = exact reduce -> gemms -> expand; rewrites ALL rows.
// 128 blocks x 256 threads.
// ===========================================================================
union SmemK2 {
    struct { float As[64][49]; float Ws[64][66]; } g;
    struct { u64 wd[256][Nsz]; unsigned char fl[256]; } e;
};

__global__ void __launch_bounds__(K2T)
k2(const float* __restrict__ w_value, const float* __restrict__ w_output,
   float* __restrict__ out) {
    __shared__ SmemK2 sm;
    __shared__ int sAny;
    const int t = threadIdx.x;

    if (t == 0) sAny = 0;
    __syncthreads();
    {
        int a = g_flags[t] | g_flags[t + 256];
        if (a) sAny = 1;
    }
    __syncthreads();
    if (!sAny) return;   // grid-uniform: out fully written by K1

    const size_t row0 = (size_t)blockIdx.x * 256;

    // ---- SLOW PATH (exact for arbitrary inputs) ----
    {
        unsigned gtid = blockIdx.x * K2T + t;   // 32768 threads >= 48*256 items
        if (gtid < 48u * 256u) {
            int bn = gtid >> 8, dd = gtid & 255;
            int bb = bn / Nsz, nn = bn % Nsz;
            float4 s = make_float4(0.f, 0.f, 0.f, 0.f);
            for (int c = 0; c < 128; c++) {
                if (g_flags[bb * 128 + c]) {
                    const float4 v = *(const float4*)(g_Upart +
                        ((size_t)(bb * 128 + c) * Nsz + nn) * Dsz + dd * 4);
                    s.x += v.x; s.y += v.y; s.z += v.z; s.w += v.w;
                }
            }
            *(float4*)(g_U + bn * Dsz + dd * 4) = s;
            float4 z4 = make_float4(0.f, 0.f, 0.f, 0.f);
            *(float4*)(g_SV + bn * Dsz + dd * 4) = z4;
            *(float4*)(g_T + bn * Dsz + dd * 4) = z4;
        }
    }
    gridbar(0);

    for (int phase = 0; phase < 2; phase++) {
        const float* A = phase ? g_SV : g_U;
        const float* W = phase ? w_output : w_value;
        float* C = phase ? g_T : g_SV;
        for (int tile = blockIdx.x; tile < 256; tile += K2BLK) {
            int e0 = (tile & 15) * 64, k0 = (tile >> 4) * 64;
            __syncthreads();
            for (int idx = t; idx < 48 * 64; idx += K2T) {
                int m = idx >> 6, kk = idx & 63;
                sm.g.As[kk][m] = A[(size_t)m * Dsz + k0 + kk];
            }
            for (int idx = t; idx < 64 * 64; idx += K2T) {
                int e = idx >> 6, kk = idx & 63;
                sm.g.Ws[kk][e] = W[(size_t)(e0 + e) * Dsz + k0 + kk];
            }
            __syncthreads();
            int ty = t >> 5, tx = t & 31;
            float a0[6][2];
            #pragma unroll
            for (int i = 0; i < 6; i++) { a0[i][0] = 0.f; a0[i][1] = 0.f; }
            for (int kk = 0; kk < 64; kk++) {
                float av[6];
                #pragma unroll
                for (int i = 0; i < 6; i++) av[i] = sm.g.As[kk][ty * 6 + i];
                float2 wv = *(const float2*)&sm.g.Ws[kk][tx * 2];
                #pragma unroll
                for (int i = 0; i < 6; i++) {
                    a0[i][0] += av[i] * wv.x;
                    a0[i][1] += av[i] * wv.y;
                }
            }
            #pragma unroll
            for (int i = 0; i < 6; i++) {
                int m = ty * 6 + i;
                atomicAdd(&C[(size_t)m * Dsz + e0 + tx * 2 + 0], a0[i][0]);
                atomicAdd(&C[(size_t)m * Dsz + e0 + tx * 2 + 1], a0[i][1]);
            }
        }
        gridbar(1 + phase);
    }

    // expand: rewrites ALL 256 rows of this block's range (exact; overwrites
    // K1's unconditional zeros with the true values).
    {
        const int b = blockIdx.x >> 5;
        const int col = t * 4;
        for (int i = t; i < 256 * Nsz; i += K2T) {
            int r = i / Nsz;
            ((u64*)sm.e.wd)[i] = g_rowflag[row0 + r] ? g_wdup[row0 * Nsz + i] : 0ull;
        }
        if (t < 256) sm.e.fl[t] = g_rowflag[row0 + t];
        ulonglong2 trp[Nsz];
        #pragma unroll
        for (int n = 0; n < Nsz; n++)
            trp[n] = *(const ulonglong2*)(g_T + (size_t)(b * Nsz + n) * Dsz + col);
        __syncthreads();

        #pragma unroll 1
        for (int r = 0; r < 256; r++) {
            ulonglong2 o; o.x = 0ull; o.y = 0ull;
            if (sm.e.fl[r]) {
                const ulonglong2* wp = (const ulonglong2*)sm.e.wd[r];
                #pragma unroll
                for (int pq = 0; pq < 6; pq++) {
                    ulonglong2 q = wp[pq];
                    ffma2(o.x, q.x, trp[2 * pq    ].x);
                    ffma2(o.y, q.x, trp[2 * pq    ].y);
                    ffma2(o.x, q.y, trp[2 * pq + 1].x);
                    ffma2(o.y, q.y, trp[2 * pq + 1].y);
                }
            }
            *(ulonglong2*)(out + (row0 + r) * Dsz + col) = o;
        }
    }
}

extern "C" void kernel_launch(void* const* d_in, const int* in_sizes, int n_in,
                              void* d_out, int out_size) {
    const float* x        = (const float*)d_in[0];
    const float* centers  = (const float*)d_in[1];
    const float* scales   = (const float*)d_in[2];
    const float* amps     = (const float*)d_in[3];
    const float* w_value  = (const float*)d_in[4];
    const float* w_output = (const float*)d_in[5];
    float* out = (float*)d_out;

    k1<<<K1BLK, 256>>>(x, centers, scales, amps, out);
    k2<<<K2BLK, K2T>>>(w_value, w_output, out);
}